// round 2
// baseline (speedup 1.0000x reference)
#include <cuda_runtime.h>
#include <cstddef>

#define N_NODES 100000
#define N_EDGES 1600000
#define DIM     128
#define DOUT    64

// ---------------- scratch (device globals; no allocation allowed) ----------
__device__ __align__(16) float g_bufA[(size_t)N_NODES * DIM];   // 51.2 MB
__device__ __align__(16) float g_bufB[(size_t)N_NODES * DIM];   // 51.2 MB
__device__ float g_dinv[N_NODES];                 // deg -> 1/sqrt(deg)
__device__ int   g_src[N_EDGES];
__device__ int   g_dst[N_EDGES];
__device__ float g_norm[N_EDGES];

// ---------------- degree / normalization ----------------------------------
__global__ void k_deg_init() {
    int i = blockIdx.x * blockDim.x + threadIdx.x;
    if (i < N_NODES) g_dinv[i] = 1.0f;            // self-loop
}

__global__ void k_deg_count(const int* __restrict__ ei) {
    int e = blockIdx.x * blockDim.x + threadIdx.x;
    if (e < N_EDGES) atomicAdd(&g_dinv[ei[N_EDGES + e]], 1.0f);
}

__global__ void k_dinv_finalize() {
    int i = blockIdx.x * blockDim.x + threadIdx.x;
    if (i < N_NODES) g_dinv[i] = rsqrtf(g_dinv[i]);
}

__global__ void k_edge_prep(const int* __restrict__ ei) {
    int e = blockIdx.x * blockDim.x + threadIdx.x;
    if (e >= N_EDGES) return;
    int s = ei[e];
    int d = ei[N_EDGES + e];
    g_src[e] = s;
    g_dst[e] = d;
    g_norm[e] = g_dinv[s] * g_dinv[d];
}

// ---------------- zero a float buffer (float4) -----------------------------
__global__ void k_zero(float4* __restrict__ p, int n4) {
    int i = blockIdx.x * blockDim.x + threadIdx.x;
    if (i < n4) p[i] = make_float4(0.f, 0.f, 0.f, 0.f);
}

// ---------------- GEMM: Y[n,NCOL] = X[n,128] @ W[128,NCOL] (+bias) ---------
// Block: 32 rows, 256 threads. K split into 2 halves of 64 (static smem <48KB).
template <int NCOL, bool BIAS>
__global__ void __launch_bounds__(256) k_gemm(
    const float* __restrict__ X, const float* __restrict__ W,
    const float* __restrict__ bias, float* __restrict__ Y, int nrows)
{
    constexpr int CG  = NCOL / 4;     // column groups of float4 (32 or 16)
    constexpr int RG  = 256 / CG;     // row groups (8 or 16)
    constexpr int RPT = 32 / RG;      // rows per thread (4 or 2)

    __shared__ float Ws[64 * NCOL];       // 64 K-rows of W
    __shared__ float Xs[32 * 68];         // 32 rows x 64 k, padded stride 68

    const int tid  = threadIdx.x;
    const int cg   = tid % CG;
    const int rg   = tid / CG;
    const int row0 = blockIdx.x * 32;

    float acc[RPT][4];
#pragma unroll
    for (int r = 0; r < RPT; ++r) {
        acc[r][0] = 0.f; acc[r][1] = 0.f; acc[r][2] = 0.f; acc[r][3] = 0.f;
    }

    for (int kt = 0; kt < 2; ++kt) {
        // load W K-half: rows kt*64 .. kt*64+63 (contiguous 64*NCOL floats)
        const float4* Wg  = (const float4*)(W + (size_t)kt * 64 * NCOL);
        float4*       Ws4 = (float4*)Ws;
#pragma unroll 4
        for (int i = tid; i < 64 * NCOL / 4; i += 256) Ws4[i] = Wg[i];

        // load X tile: 32 rows x 64 cols (16 float4 per row)
        for (int i = tid; i < 32 * 16; i += 256) {
            int r  = i / 16;
            int kk = i % 16;
            float4 v = make_float4(0.f, 0.f, 0.f, 0.f);
            if (row0 + r < nrows)
                v = ((const float4*)(X + (size_t)(row0 + r) * DIM + kt * 64))[kk];
            ((float4*)(Xs + r * 68))[kk] = v;
        }
        __syncthreads();

#pragma unroll 8
        for (int k = 0; k < 64; ++k) {
            float4 w = ((const float4*)(Ws + k * NCOL))[cg];
#pragma unroll
            for (int r = 0; r < RPT; ++r) {
                float xv = Xs[(rg * RPT + r) * 68 + k];
                acc[r][0] += xv * w.x;
                acc[r][1] += xv * w.y;
                acc[r][2] += xv * w.z;
                acc[r][3] += xv * w.w;
            }
        }
        __syncthreads();
    }

#pragma unroll
    for (int r = 0; r < RPT; ++r) {
        int row = row0 + rg * RPT + r;
        if (row < nrows) {
            float4 o = make_float4(acc[r][0], acc[r][1], acc[r][2], acc[r][3]);
            if (BIAS) {
                float4 b = ((const float4*)bias)[cg];
                o.x += b.x; o.y += b.y; o.z += b.z; o.w += b.w;
            }
            ((float4*)(Y + (size_t)row * NCOL))[cg] = o;
        }
    }
}

// ---------------- edge scatter: B[dst] += A[src] * norm  (warp per edge) ---
__global__ void __launch_bounds__(256) k_scatter(
    const float* __restrict__ A, float* __restrict__ B)
{
    int w    = (blockIdx.x * 256 + threadIdx.x) >> 5;
    int lane = threadIdx.x & 31;
    if (w >= N_EDGES) return;
    int   s  = g_src[w];
    int   d  = g_dst[w];
    float nm = g_norm[w];
    float4 v = ((const float4*)(A + (size_t)s * DIM))[lane];
    v.x *= nm; v.y *= nm; v.z *= nm; v.w *= nm;
    atomicAdd(((float4*)(B + (size_t)d * DIM)) + lane, v);   // RED.128 (sm_90+)
}

// ---------------- self-loop + bias + relu (in place into B) ----------------
__global__ void k_bias_relu_self(
    const float* __restrict__ A, float* __restrict__ B,
    const float* __restrict__ bias)
{
    int i = blockIdx.x * blockDim.x + threadIdx.x;   // N_NODES*32 lanes
    if (i >= N_NODES * 32) return;
    int node = i >> 5, lane = i & 31;
    float di = g_dinv[node];
    float sn = di * di;
    float4 a  = ((const float4*)(A + (size_t)node * DIM))[lane];
    float4 b  = ((const float4*)(B + (size_t)node * DIM))[lane];
    float4 bb = ((const float4*)bias)[lane];
    float4 o;
    o.x = fmaxf(b.x + a.x * sn + bb.x, 0.f);
    o.y = fmaxf(b.y + a.y * sn + bb.y, 0.f);
    o.z = fmaxf(b.z + a.z * sn + bb.z, 0.f);
    o.w = fmaxf(b.w + a.w * sn + bb.w, 0.f);
    ((float4*)(B + (size_t)node * DIM))[lane] = o;
}

// ---------------- launch ----------------------------------------------------
extern "C" void kernel_launch(void* const* d_in, const int* in_sizes, int n_in,
                              void* d_out, int out_size)
{
    const float* x    = (const float*)d_in[0];
    const int*   ei   = (const int*)d_in[1];     // JAX x64 disabled -> int32
    const float* W1   = (const float*)d_in[2];
    const float* b1   = (const float*)d_in[3];
    const float* W2   = (const float*)d_in[4];
    const float* b2   = (const float*)d_in[5];
    const float* fcW  = (const float*)d_in[6];
    const float* fcb  = (const float*)d_in[7];
    float*       out  = (float*)d_out;

    void *pA_, *pB_;
    cudaGetSymbolAddress(&pA_, g_bufA);
    cudaGetSymbolAddress(&pB_, g_bufB);
    float* bufA = (float*)pA_;
    float* bufB = (float*)pB_;

    const int TB = 256;
    const int gN  = (N_NODES + TB - 1) / TB;
    const int gE  = (N_EDGES + TB - 1) / TB;
    const int gZ  = (N_NODES * 32 + TB - 1) / TB;          // float4 lanes per buffer
    const int gSc = (int)(((long long)N_EDGES * 32 + TB - 1) / TB);
    const int gG  = (N_NODES + 31) / 32;

    // normalization precompute
    k_deg_init<<<gN, TB>>>();
    k_deg_count<<<gE, TB>>>(ei);
    k_dinv_finalize<<<gN, TB>>>();
    k_edge_prep<<<gE, TB>>>(ei);

    // layer 1: bufA = x@W1 ; bufB = scatter(bufA) ; bufB = relu(bufB + self + b1)
    k_gemm<DIM, false><<<gG, TB>>>(x, W1, nullptr, bufA, N_NODES);
    k_zero<<<gZ, TB>>>((float4*)bufB, N_NODES * 32);
    k_scatter<<<gSc, TB>>>(bufA, bufB);
    k_bias_relu_self<<<gZ, TB>>>(bufA, bufB, b1);

    // layer 2: bufA = bufB@W2 ; bufB = scatter(bufA) ; relu
    k_gemm<DIM, false><<<gG, TB>>>(bufB, W2, nullptr, bufA, N_NODES);
    k_zero<<<gZ, TB>>>((float4*)bufB, N_NODES * 32);
    k_scatter<<<gSc, TB>>>(bufA, bufB);
    k_bias_relu_self<<<gZ, TB>>>(bufA, bufB, b2);

    // fc: out = bufB @ fc_W + fc_b
    k_gemm<DOUT, true><<<gG, TB>>>(bufB, fcW, fcb, out, N_NODES);
}

// round 3
// speedup vs baseline: 1.2297x; 1.2297x over previous
#include <cuda_runtime.h>
#include <cstddef>

#define N_NODES 100000
#define N_EDGES 1600000
#define DIM     128
#define DOUT    64
#define SCAN_T  1024
#define CHUNK   ((N_NODES + SCAN_T - 1) / SCAN_T)   // 98

// ---------------- scratch (device globals; no allocation allowed) ----------
__device__ __align__(16) float g_bufA[(size_t)N_NODES * DIM];   // 51.2 MB
__device__ __align__(16) float g_bufB[(size_t)N_NODES * DIM];   // 51.2 MB
__device__ float g_dinv[N_NODES];
__device__ int   g_deg[N_NODES];        // in-degree (without self loop)
__device__ int   g_rowstart[N_NODES];
__device__ int   g_cursor[N_NODES];
__device__ int   g_csr_src[N_EDGES];
__device__ float g_csr_norm[N_EDGES];

// ---------------- degree / normalization / CSR -----------------------------
__global__ void k_deg_zero() {
    int i = blockIdx.x * blockDim.x + threadIdx.x;
    if (i < N_NODES) g_deg[i] = 0;
}

__global__ void k_deg_count(const int* __restrict__ ei) {
    int e = blockIdx.x * blockDim.x + threadIdx.x;
    if (e < N_EDGES) atomicAdd(&g_deg[ei[N_EDGES + e]], 1);
}

__global__ void k_dinv_finalize() {
    int i = blockIdx.x * blockDim.x + threadIdx.x;
    if (i < N_NODES) g_dinv[i] = rsqrtf((float)(g_deg[i] + 1));  // +1 self loop
}

// single-block exclusive scan of g_deg -> g_rowstart (+ cursor copy)
__global__ void __launch_bounds__(SCAN_T) k_scan() {
    __shared__ int sums[SCAN_T];
    int t = threadIdx.x;
    int lo = t * CHUNK;
    int hi = min(lo + CHUNK, N_NODES);
    int s = 0;
    for (int i = lo; i < hi; ++i) s += g_deg[i];
    sums[t] = s;
    __syncthreads();
    // Hillis-Steele inclusive scan on sums
    for (int off = 1; off < SCAN_T; off <<= 1) {
        int v = (t >= off) ? sums[t - off] : 0;
        __syncthreads();
        sums[t] += v;
        __syncthreads();
    }
    int run = (t == 0) ? 0 : sums[t - 1];   // exclusive base
    for (int i = lo; i < hi; ++i) {
        g_rowstart[i] = run;
        g_cursor[i]   = run;
        run += g_deg[i];
    }
}

__global__ void k_csr_fill(const int* __restrict__ ei) {
    int e = blockIdx.x * blockDim.x + threadIdx.x;
    if (e >= N_EDGES) return;
    int s = ei[e];
    int d = ei[N_EDGES + e];
    int pos = atomicAdd(&g_cursor[d], 1);
    g_csr_src[pos]  = s;
    g_csr_norm[pos] = g_dinv[s] * g_dinv[d];
}

// ---------------- GEMM: Y[n,NCOL] = X[n,128] @ W[128,NCOL] (+bias) ---------
// f32x2 packed FMA inner loop (2x fp32 throughput on sm_103a)
template <int NCOL, bool BIAS>
__global__ void __launch_bounds__(256) k_gemm(
    const float* __restrict__ X, const float* __restrict__ W,
    const float* __restrict__ bias, float* __restrict__ Y, int nrows)
{
    constexpr int CG  = NCOL / 4;     // float4 column groups (32 or 16)
    constexpr int RG  = 256 / CG;     // row groups (8 or 16)
    constexpr int RPT = 32 / RG;      // rows per thread (4 or 2)

    __shared__ float Ws[64 * NCOL];
    __shared__ float Xs[32 * 68];

    const int tid  = threadIdx.x;
    const int cg   = tid % CG;
    const int rg   = tid / CG;
    const int row0 = blockIdx.x * 32;

    unsigned long long accL[RPT], accH[RPT];
#pragma unroll
    for (int r = 0; r < RPT; ++r) { accL[r] = 0ull; accH[r] = 0ull; }

    for (int kt = 0; kt < 2; ++kt) {
        const float4* Wg  = (const float4*)(W + (size_t)kt * 64 * NCOL);
        float4*       Ws4 = (float4*)Ws;
#pragma unroll 4
        for (int i = tid; i < 64 * NCOL / 4; i += 256) Ws4[i] = Wg[i];

        for (int i = tid; i < 32 * 16; i += 256) {
            int r  = i / 16;
            int kk = i % 16;
            float4 v = make_float4(0.f, 0.f, 0.f, 0.f);
            if (row0 + r < nrows)
                v = ((const float4*)(X + (size_t)(row0 + r) * DIM + kt * 64))[kk];
            ((float4*)(Xs + r * 68))[kk] = v;
        }
        __syncthreads();

#pragma unroll 8
        for (int k = 0; k < 64; ++k) {
            ulonglong2 w = *((const ulonglong2*)(Ws + k * NCOL) + cg);
#pragma unroll
            for (int r = 0; r < RPT; ++r) {
                unsigned xu = __float_as_uint(Xs[(rg * RPT + r) * 68 + k]);
                unsigned long long xp;
                asm("mov.b64 %0, {%1, %1};" : "=l"(xp) : "r"(xu));
                asm("fma.rn.f32x2 %0, %1, %2, %0;" : "+l"(accL[r]) : "l"(xp), "l"(w.x));
                asm("fma.rn.f32x2 %0, %1, %2, %0;" : "+l"(accH[r]) : "l"(xp), "l"(w.y));
            }
        }
        __syncthreads();
    }

#pragma unroll
    for (int r = 0; r < RPT; ++r) {
        int row = row0 + rg * RPT + r;
        if (row < nrows) {
            float2 lo, hi;
            asm("mov.b64 {%0, %1}, %2;" : "=f"(lo.x), "=f"(lo.y) : "l"(accL[r]));
            asm("mov.b64 {%0, %1}, %2;" : "=f"(hi.x), "=f"(hi.y) : "l"(accH[r]));
            float4 o = make_float4(lo.x, lo.y, hi.x, hi.y);
            if (BIAS) {
                float4 b = ((const float4*)bias)[cg];
                o.x += b.x; o.y += b.y; o.z += b.z; o.w += b.w;
            }
            ((float4*)(Y + (size_t)row * NCOL))[cg] = o;
        }
    }
}

// ---------------- CSR aggregation + self-loop + bias + relu ----------------
// warp per node, register accumulation, single write; no atomics.
__global__ void __launch_bounds__(256) k_aggregate(
    const float* __restrict__ A, float* __restrict__ B,
    const float* __restrict__ bias)
{
    int node = (blockIdx.x * 256 + threadIdx.x) >> 5;
    int lane = threadIdx.x & 31;
    if (node >= N_NODES) return;

    const float4* A4 = (const float4*)A;
    int beg = g_rowstart[node];
    int cnt = g_deg[node];

    float4 acc0 = make_float4(0.f, 0.f, 0.f, 0.f);
    float4 acc1 = make_float4(0.f, 0.f, 0.f, 0.f);

    int j = 0;
    for (; j + 2 <= cnt; j += 2) {
        int   s0 = g_csr_src[beg + j];
        int   s1 = g_csr_src[beg + j + 1];
        float n0 = g_csr_norm[beg + j];
        float n1 = g_csr_norm[beg + j + 1];
        float4 v0 = A4[(size_t)s0 * 32 + lane];
        float4 v1 = A4[(size_t)s1 * 32 + lane];
        acc0.x += v0.x * n0; acc0.y += v0.y * n0;
        acc0.z += v0.z * n0; acc0.w += v0.w * n0;
        acc1.x += v1.x * n1; acc1.y += v1.y * n1;
        acc1.z += v1.z * n1; acc1.w += v1.w * n1;
    }
    if (j < cnt) {
        int   s0 = g_csr_src[beg + j];
        float n0 = g_csr_norm[beg + j];
        float4 v0 = A4[(size_t)s0 * 32 + lane];
        acc0.x += v0.x * n0; acc0.y += v0.y * n0;
        acc0.z += v0.z * n0; acc0.w += v0.w * n0;
    }

    float di = g_dinv[node];
    float sn = di * di;
    float4 self = A4[(size_t)node * 32 + lane];
    float4 bb   = ((const float4*)bias)[lane];
    float4 o;
    o.x = fmaxf(acc0.x + acc1.x + self.x * sn + bb.x, 0.f);
    o.y = fmaxf(acc0.y + acc1.y + self.y * sn + bb.y, 0.f);
    o.z = fmaxf(acc0.z + acc1.z + self.z * sn + bb.z, 0.f);
    o.w = fmaxf(acc0.w + acc1.w + self.w * sn + bb.w, 0.f);
    ((float4*)(B + (size_t)node * DIM))[lane] = o;
}

// ---------------- launch ----------------------------------------------------
extern "C" void kernel_launch(void* const* d_in, const int* in_sizes, int n_in,
                              void* d_out, int out_size)
{
    const float* x    = (const float*)d_in[0];
    const int*   ei   = (const int*)d_in[1];     // int32 (JAX x64 disabled)
    const float* W1   = (const float*)d_in[2];
    const float* b1   = (const float*)d_in[3];
    const float* W2   = (const float*)d_in[4];
    const float* b2   = (const float*)d_in[5];
    const float* fcW  = (const float*)d_in[6];
    const float* fcb  = (const float*)d_in[7];
    float*       out  = (float*)d_out;

    void *pA_, *pB_;
    cudaGetSymbolAddress(&pA_, g_bufA);
    cudaGetSymbolAddress(&pB_, g_bufB);
    float* bufA = (float*)pA_;
    float* bufB = (float*)pB_;

    const int TB = 256;
    const int gN  = (N_NODES + TB - 1) / TB;
    const int gE  = (N_EDGES + TB - 1) / TB;
    const int gG  = (N_NODES + 31) / 32;
    const int gAg = (N_NODES * 32 + TB - 1) / TB;   // warp per node

    // CSR precompute
    k_deg_zero<<<gN, TB>>>();
    k_deg_count<<<gE, TB>>>(ei);
    k_dinv_finalize<<<gN, TB>>>();
    k_scan<<<1, SCAN_T>>>();
    k_csr_fill<<<gE, TB>>>(ei);

    // layer 1
    k_gemm<DIM, false><<<gG, TB>>>(x, W1, nullptr, bufA, N_NODES);
    k_aggregate<<<gAg, TB>>>(bufA, bufB, b1);

    // layer 2
    k_gemm<DIM, false><<<gG, TB>>>(bufB, W2, nullptr, bufA, N_NODES);
    k_aggregate<<<gAg, TB>>>(bufA, bufB, b2);

    // fc
    k_gemm<DOUT, true><<<gG, TB>>>(bufB, fcW, fcb, out, N_NODES);
}

// round 4
// speedup vs baseline: 1.6931x; 1.3769x over previous
#include <cuda_runtime.h>
#include <cstddef>

#define N_NODES 100000
#define N_EDGES 1600000
#define DIM     128
#define DOUT    64

// ---------------- scratch (device globals; no allocation allowed) ----------
__device__ __align__(16) float g_bufA[(size_t)N_NODES * DIM];   // 51.2 MB
__device__ __align__(16) float g_bufB[(size_t)N_NODES * DIM];   // 51.2 MB
__device__ float g_dinv[N_NODES];
__device__ int   g_deg[N_NODES];        // in-degree (without self loop)
__device__ int   g_rowstart[N_NODES];
__device__ int   g_cursor[N_NODES];
__device__ int   g_csr_src[N_EDGES];
__device__ float g_csr_norm[N_EDGES];
__device__ int   g_total;               // range allocator counter

// ---------------- degree / normalization / CSR -----------------------------
__global__ void k_deg_zero() {
    int i = blockIdx.x * blockDim.x + threadIdx.x;
    if (i < N_NODES) g_deg[i] = 0;
    if (i == 0) g_total = 0;
}

__global__ void k_deg_count(const int* __restrict__ ei) {
    int e = blockIdx.x * blockDim.x + threadIdx.x;
    if (e < N_EDGES) atomicAdd(&g_deg[ei[N_EDGES + e]], 1);
}

// block-parallel range allocation: block scans its 1024 degs, grabs a global
// range with ONE atomicAdd, writes rowstart/cursor. Range ORDER is irrelevant
// (CSR fill order is already arbitrary). Also computes dinv here.
__global__ void __launch_bounds__(1024) k_rowstart() {
    int i    = blockIdx.x * 1024 + threadIdx.x;
    int lane = threadIdx.x & 31;
    int wid  = threadIdx.x >> 5;
    int deg  = (i < N_NODES) ? g_deg[i] : 0;

    // warp inclusive scan
    int v = deg;
#pragma unroll
    for (int off = 1; off < 32; off <<= 1) {
        int t = __shfl_up_sync(0xffffffffu, v, off);
        if (lane >= off) v += t;
    }

    __shared__ int wsum[32];
    __shared__ int base;
    if (lane == 31) wsum[wid] = v;
    __syncthreads();
    if (wid == 0) {
        int wv = wsum[lane];
#pragma unroll
        for (int off = 1; off < 32; off <<= 1) {
            int t = __shfl_up_sync(0xffffffffu, wv, off);
            if (lane >= off) wv += t;
        }
        wsum[lane] = wv;                 // inclusive scan of warp sums
        if (lane == 31) base = atomicAdd(&g_total, wv);
    }
    __syncthreads();

    int excl = base + (wid > 0 ? wsum[wid - 1] : 0) + v - deg;
    if (i < N_NODES) {
        g_rowstart[i] = excl;
        g_cursor[i]   = excl;
        g_dinv[i]     = rsqrtf((float)(deg + 1));   // +1 self loop
    }
}

__global__ void k_csr_fill(const int* __restrict__ ei) {
    int e = blockIdx.x * blockDim.x + threadIdx.x;
    if (e >= N_EDGES) return;
    int s = ei[e];
    int d = ei[N_EDGES + e];
    int pos = atomicAdd(&g_cursor[d], 1);
    g_csr_src[pos]  = s;
    g_csr_norm[pos] = g_dinv[s] * g_dinv[d];
}

// ---------------- GEMM: Y[n,NCOL] = X[n,128] @ W[128,NCOL] (+bias) ---------
// f32x2 packed FMA inner loop (2x fp32 throughput on sm_103a)
template <int NCOL, bool BIAS>
__global__ void __launch_bounds__(256) k_gemm(
    const float* __restrict__ X, const float* __restrict__ W,
    const float* __restrict__ bias, float* __restrict__ Y, int nrows)
{
    constexpr int CG  = NCOL / 4;     // float4 column groups (32 or 16)
    constexpr int RG  = 256 / CG;     // row groups (8 or 16)
    constexpr int RPT = 32 / RG;      // rows per thread (4 or 2)

    __shared__ float Ws[64 * NCOL];
    __shared__ float Xs[32 * 68];

    const int tid  = threadIdx.x;
    const int cg   = tid % CG;
    const int rg   = tid / CG;
    const int row0 = blockIdx.x * 32;

    unsigned long long accL[RPT], accH[RPT];
#pragma unroll
    for (int r = 0; r < RPT; ++r) { accL[r] = 0ull; accH[r] = 0ull; }

    for (int kt = 0; kt < 2; ++kt) {
        const float4* Wg  = (const float4*)(W + (size_t)kt * 64 * NCOL);
        float4*       Ws4 = (float4*)Ws;
#pragma unroll 4
        for (int i = tid; i < 64 * NCOL / 4; i += 256) Ws4[i] = Wg[i];

        for (int i = tid; i < 32 * 16; i += 256) {
            int r  = i / 16;
            int kk = i % 16;
            float4 v = make_float4(0.f, 0.f, 0.f, 0.f);
            if (row0 + r < nrows)
                v = ((const float4*)(X + (size_t)(row0 + r) * DIM + kt * 64))[kk];
            ((float4*)(Xs + r * 68))[kk] = v;
        }
        __syncthreads();

#pragma unroll 8
        for (int k = 0; k < 64; ++k) {
            ulonglong2 w = *((const ulonglong2*)(Ws + k * NCOL) + cg);
#pragma unroll
            for (int r = 0; r < RPT; ++r) {
                unsigned xu = __float_as_uint(Xs[(rg * RPT + r) * 68 + k]);
                unsigned long long xp;
                asm("mov.b64 %0, {%1, %1};" : "=l"(xp) : "r"(xu));
                asm("fma.rn.f32x2 %0, %1, %2, %0;" : "+l"(accL[r]) : "l"(xp), "l"(w.x));
                asm("fma.rn.f32x2 %0, %1, %2, %0;" : "+l"(accH[r]) : "l"(xp), "l"(w.y));
            }
        }
        __syncthreads();
    }

#pragma unroll
    for (int r = 0; r < RPT; ++r) {
        int row = row0 + rg * RPT + r;
        if (row < nrows) {
            float2 lo, hi;
            asm("mov.b64 {%0, %1}, %2;" : "=f"(lo.x), "=f"(lo.y) : "l"(accL[r]));
            asm("mov.b64 {%0, %1}, %2;" : "=f"(hi.x), "=f"(hi.y) : "l"(accH[r]));
            float4 o = make_float4(lo.x, lo.y, hi.x, hi.y);
            if (BIAS) {
                float4 b = ((const float4*)bias)[cg];
                o.x += b.x; o.y += b.y; o.z += b.z; o.w += b.w;
            }
            ((float4*)(Y + (size_t)row * NCOL))[cg] = o;
        }
    }
}

// ---------------- CSR aggregation + self-loop + bias + relu ----------------
// warp per node, register accumulation, single write; no atomics.
__global__ void __launch_bounds__(256) k_aggregate(
    const float* __restrict__ A, float* __restrict__ B,
    const float* __restrict__ bias)
{
    int node = (blockIdx.x * 256 + threadIdx.x) >> 5;
    int lane = threadIdx.x & 31;
    if (node >= N_NODES) return;

    const float4* A4 = (const float4*)A;
    int beg = g_rowstart[node];
    int cnt = g_deg[node];

    float4 acc0 = make_float4(0.f, 0.f, 0.f, 0.f);
    float4 acc1 = make_float4(0.f, 0.f, 0.f, 0.f);

    int j = 0;
    for (; j + 2 <= cnt; j += 2) {
        int   s0 = g_csr_src[beg + j];
        int   s1 = g_csr_src[beg + j + 1];
        float n0 = g_csr_norm[beg + j];
        float n1 = g_csr_norm[beg + j + 1];
        float4 v0 = A4[(size_t)s0 * 32 + lane];
        float4 v1 = A4[(size_t)s1 * 32 + lane];
        acc0.x += v0.x * n0; acc0.y += v0.y * n0;
        acc0.z += v0.z * n0; acc0.w += v0.w * n0;
        acc1.x += v1.x * n1; acc1.y += v1.y * n1;
        acc1.z += v1.z * n1; acc1.w += v1.w * n1;
    }
    if (j < cnt) {
        int   s0 = g_csr_src[beg + j];
        float n0 = g_csr_norm[beg + j];
        float4 v0 = A4[(size_t)s0 * 32 + lane];
        acc0.x += v0.x * n0; acc0.y += v0.y * n0;
        acc0.z += v0.z * n0; acc0.w += v0.w * n0;
    }

    float di = g_dinv[node];
    float sn = di * di;
    float4 self = A4[(size_t)node * 32 + lane];
    float4 bb   = ((const float4*)bias)[lane];
    float4 o;
    o.x = fmaxf(acc0.x + acc1.x + self.x * sn + bb.x, 0.f);
    o.y = fmaxf(acc0.y + acc1.y + self.y * sn + bb.y, 0.f);
    o.z = fmaxf(acc0.z + acc1.z + self.z * sn + bb.z, 0.f);
    o.w = fmaxf(acc0.w + acc1.w + self.w * sn + bb.w, 0.f);
    ((float4*)(B + (size_t)node * DIM))[lane] = o;
}

// ---------------- launch ----------------------------------------------------
extern "C" void kernel_launch(void* const* d_in, const int* in_sizes, int n_in,
                              void* d_out, int out_size)
{
    const float* x    = (const float*)d_in[0];
    const int*   ei   = (const int*)d_in[1];     // int32 (JAX x64 disabled)
    const float* W1   = (const float*)d_in[2];
    const float* b1   = (const float*)d_in[3];
    const float* W2   = (const float*)d_in[4];
    const float* b2   = (const float*)d_in[5];
    const float* fcW  = (const float*)d_in[6];
    const float* fcb  = (const float*)d_in[7];
    float*       out  = (float*)d_out;

    void *pA_, *pB_;
    cudaGetSymbolAddress(&pA_, g_bufA);
    cudaGetSymbolAddress(&pB_, g_bufB);
    float* bufA = (float*)pA_;
    float* bufB = (float*)pB_;

    const int TB = 256;
    const int gN  = (N_NODES + TB - 1) / TB;
    const int gE  = (N_EDGES + TB - 1) / TB;
    const int gG  = (N_NODES + 31) / 32;
    const int gAg = (N_NODES * 32 + TB - 1) / TB;   // warp per node
    const int gRS = (N_NODES + 1023) / 1024;

    // CSR precompute
    k_deg_zero<<<gN, TB>>>();
    k_deg_count<<<gE, TB>>>(ei);
    k_rowstart<<<gRS, 1024>>>();
    k_csr_fill<<<gE, TB>>>(ei);

    // layer 1
    k_gemm<DIM, false><<<gG, TB>>>(x, W1, nullptr, bufA, N_NODES);
    k_aggregate<<<gAg, TB>>>(bufA, bufB, b1);

    // layer 2
    k_gemm<DIM, false><<<gG, TB>>>(bufB, W2, nullptr, bufA, N_NODES);
    k_aggregate<<<gAg, TB>>>(bufA, bufB, b2);

    // fc
    k_gemm<DOUT, true><<<gG, TB>>>(bufB, fcW, fcb, out, N_NODES);
}